// round 16
// baseline (speedup 1.0000x reference)
#include <cuda_runtime.h>
#include <cuda_fp16.h>
#include <math.h>
#include <stdint.h>

// ---------------------------------------------------------------------------
// Problem constants
// ---------------------------------------------------------------------------
#define D_MODEL 1024
#define DFF     4096
#define NLAYERS 8
#define BATCH   4
#define SEQ     2048
#define NTOK    (BATCH * SEQ)      // 8192
#define EPS     1e-5f

// ---------------------------------------------------------------------------
// Device scratch (allocation-free rule: __device__ globals)
// ---------------------------------------------------------------------------
__device__ __half g_ln16 [NTOK * D_MODEL];
__device__ __half g_qkv16[3 * NTOK * D_MODEL];
__device__ __half g_sc16 [BATCH * SEQ * SEQ];     // fp16 attention logits
__device__ __half g_at16 [BATCH * SEQ * SEQ];     // fp16 attention weights
__device__ __half g_hid16[NTOK * DFF];
// fp16 weights; QKV interleaved per layer: [L][3][D*D]
__device__ __half g_Wqkv16[NLAYERS * 3 * D_MODEL * D_MODEL];
__device__ __half g_W116[NLAYERS * D_MODEL * DFF];
__device__ __half g_W216[NLAYERS * DFF * D_MODEL];
__device__ float  g_bqkv[NLAYERS * 3 * D_MODEL];

// ---------------------------------------------------------------------------
// PTX helpers
// ---------------------------------------------------------------------------
__device__ __forceinline__ uint32_t smem_u32(const void* p) {
    uint32_t a;
    asm("{ .reg .u64 t; cvta.to.shared.u64 t, %1; cvt.u32.u64 %0, t; }"
        : "=r"(a) : "l"(p));
    return a;
}

__device__ __forceinline__ void ldsm_x4(uint32_t* r, uint32_t addr) {
    asm volatile("ldmatrix.sync.aligned.m8n8.x4.shared.b16 {%0,%1,%2,%3}, [%4];"
                 : "=r"(r[0]), "=r"(r[1]), "=r"(r[2]), "=r"(r[3]) : "r"(addr));
}

__device__ __forceinline__ void ldsm_x4_t(uint32_t* r, uint32_t addr) {
    asm volatile("ldmatrix.sync.aligned.m8n8.x4.trans.shared.b16 {%0,%1,%2,%3}, [%4];"
                 : "=r"(r[0]), "=r"(r[1]), "=r"(r[2]), "=r"(r[3]) : "r"(addr));
}

__device__ __forceinline__ void mma_f16(float* c, const uint32_t* a, const uint32_t* b) {
    asm volatile(
        "mma.sync.aligned.m16n8k16.row.col.f32.f16.f16.f32 "
        "{%0,%1,%2,%3}, {%4,%5,%6,%7}, {%8,%9}, {%0,%1,%2,%3};"
        : "+f"(c[0]), "+f"(c[1]), "+f"(c[2]), "+f"(c[3])
        : "r"(a[0]), "r"(a[1]), "r"(a[2]), "r"(a[3]), "r"(b[0]), "r"(b[1]));
}

__device__ __forceinline__ void cp_async16(uint32_t saddr, const void* gptr) {
    asm volatile("cp.async.cg.shared.global [%0], [%1], 16;"
                 :: "r"(saddr), "l"(gptr) : "memory");
}
__device__ __forceinline__ void cp_commit() {
    asm volatile("cp.async.commit_group;" ::: "memory");
}
__device__ __forceinline__ void cp_wait_all() {
    asm volatile("cp.async.wait_group 0;" ::: "memory");
}

__device__ __forceinline__ uint32_t pack2h(float a, float b) {
    __half ha = __float2half_rn(a), hb = __float2half_rn(b);
    return ((uint32_t)__half_as_ushort(hb) << 16) | __half_as_ushort(ha);
}

// ---------------------------------------------------------------------------
// Weight conversion kernels (fp32 -> fp16), merged
// ---------------------------------------------------------------------------
__global__ __launch_bounds__(256)
void conv_qkv_kernel(const float* __restrict__ Wq,
                     const float* __restrict__ Wk,
                     const float* __restrict__ Wv,
                     __half* __restrict__ out, int n4, int S4)
{
    int i = blockIdx.x * 256 + threadIdx.x;
    if (i >= n4) return;
    int j = blockIdx.z;
    const float* in = (j == 0) ? Wq : (j == 1) ? Wk : Wv;
    int l = i / S4;
    int rem = i - l * S4;
    int d = (l * 3 + j) * S4 + rem;
    float4 v = ((const float4*)in)[i];
    ((uint2*)out)[d] = make_uint2(pack2h(v.x, v.y), pack2h(v.z, v.w));
}

__global__ __launch_bounds__(256)
void conv2_kernel(const float* __restrict__ W1, const float* __restrict__ W2,
                  __half* __restrict__ o1, __half* __restrict__ o2, int n4)
{
    int i = blockIdx.x * 256 + threadIdx.x;
    if (i >= n4) return;
    const float* in = blockIdx.z ? W2 : W1;
    __half* out = blockIdx.z ? o2 : o1;
    float4 v = ((const float4*)in)[i];
    ((uint2*)out)[i] = make_uint2(pack2h(v.x, v.y), pack2h(v.z, v.w));
}

__global__ __launch_bounds__(256)
void concat_bias_kernel(const float* __restrict__ bq,
                        const float* __restrict__ bk,
                        const float* __restrict__ bv,
                        float* __restrict__ out)
{
    int i = blockIdx.x * 256 + threadIdx.x;
    int l = i / D_MODEL;
    int d = i - l * D_MODEL;
    out[(l * 3 + 0) * D_MODEL + d] = bq[i];
    out[(l * 3 + 1) * D_MODEL + d] = bk[i];
    out[(l * 3 + 2) * D_MODEL + d] = bv[i];
}

// ---------------------------------------------------------------------------
// Embedding + sinusoidal PE
// ---------------------------------------------------------------------------
__global__ __launch_bounds__(256)
void embed_kernel(const int* __restrict__ tokens,
                  const float* __restrict__ emb,
                  float* __restrict__ out)
{
    int row = blockIdx.x;
    int s   = row & (SEQ - 1);
    int tok = tokens[row];
    int d   = threadIdx.x * 4;

    float4 e = *(const float4*)&emb[(size_t)tok * D_MODEL + d];
    float o[4] = { e.x, e.y, e.z, e.w };
#pragma unroll
    for (int i = 0; i < 4; i++) {
        int dd = d + i;
        float freq = expf((float)(dd & ~1) * (-9.210340371976184f / (float)D_MODEL));
        float a = (float)s * freq;
        o[i] += (dd & 1) ? cosf(a) : sinf(a);
    }
    *(float4*)&out[(size_t)row * D_MODEL + d] = make_float4(o[0], o[1], o[2], o[3]);
}

// ---------------------------------------------------------------------------
// LayerNorm: fp32 in -> fp16 out
// ---------------------------------------------------------------------------
__global__ __launch_bounds__(256)
void ln_kernel(const float* __restrict__ x,
               const float* __restrict__ g,
               const float* __restrict__ b,
               __half* __restrict__ out)
{
    __shared__ float red[8];
    __shared__ float s_stat;

    int row = blockIdx.x;
    int tid = threadIdx.x;
    const float4* xr = (const float4*)(x + (size_t)row * D_MODEL);
    float4 v = xr[tid];

    float s = v.x + v.y + v.z + v.w;
#pragma unroll
    for (int o = 16; o > 0; o >>= 1) s += __shfl_xor_sync(0xffffffffu, s, o);
    if ((tid & 31) == 0) red[tid >> 5] = s;
    __syncthreads();
    if (tid == 0) {
        float t = 0.f;
#pragma unroll
        for (int i = 0; i < 8; i++) t += red[i];
        s_stat = t * (1.0f / D_MODEL);
    }
    __syncthreads();
    float mean = s_stat;

    float4 d;
    d.x = v.x - mean; d.y = v.y - mean; d.z = v.z - mean; d.w = v.w - mean;

    float s2 = d.x * d.x + d.y * d.y + d.z * d.z + d.w * d.w;
#pragma unroll
    for (int o = 16; o > 0; o >>= 1) s2 += __shfl_xor_sync(0xffffffffu, s2, o);
    if ((tid & 31) == 0) red[tid >> 5] = s2;
    __syncthreads();
    if (tid == 0) {
        float t = 0.f;
#pragma unroll
        for (int i = 0; i < 8; i++) t += red[i];
        s_stat = rsqrtf(t * (1.0f / D_MODEL) + EPS);
    }
    __syncthreads();
    float rstd = s_stat;

    float4 gg = *(const float4*)&g[tid * 4];
    float4 bb = *(const float4*)&b[tid * 4];
    float4 o4;
    o4.x = d.x * rstd * gg.x + bb.x;
    o4.y = d.y * rstd * gg.y + bb.y;
    o4.z = d.z * rstd * gg.z + bb.z;
    o4.w = d.w * rstd * gg.w + bb.w;

    ((uint2*)(out + (size_t)row * D_MODEL))[tid] =
        make_uint2(pack2h(o4.x, o4.y), pack2h(o4.z, o4.w));
}

// ---------------------------------------------------------------------------
// Softmax: fp16 logits in -> fp16 weights out
// ---------------------------------------------------------------------------
__device__ __forceinline__ void unpack8(uint4 u, float* f) {
    float2 a = __half22float2(*(__half2*)&u.x);
    float2 b = __half22float2(*(__half2*)&u.y);
    float2 c = __half22float2(*(__half2*)&u.z);
    float2 d = __half22float2(*(__half2*)&u.w);
    f[0] = a.x; f[1] = a.y; f[2] = b.x; f[3] = b.y;
    f[4] = c.x; f[5] = c.y; f[6] = d.x; f[7] = d.y;
}

__global__ __launch_bounds__(256)
void softmax_kernel(const __half* __restrict__ sc, __half* __restrict__ oh)
{
    __shared__ float red[8];
    __shared__ float s_val;

    size_t row = blockIdx.x;
    const uint4* p = (const uint4*)(sc + row * SEQ);
    int tid = threadIdx.x;

    float v[8];
    unpack8(p[tid], v);

    float m = v[0];
#pragma unroll
    for (int i = 1; i < 8; i++) m = fmaxf(m, v[i]);
#pragma unroll
    for (int o = 16; o > 0; o >>= 1) m = fmaxf(m, __shfl_xor_sync(0xffffffffu, m, o));
    if ((tid & 31) == 0) red[tid >> 5] = m;
    __syncthreads();
    if (tid == 0) {
        float t = red[0];
#pragma unroll
        for (int i = 1; i < 8; i++) t = fmaxf(t, red[i]);
        s_val = t;
    }
    __syncthreads();
    m = s_val;

    float s = 0.f;
#pragma unroll
    for (int i = 0; i < 8; i++) { v[i] = __expf(v[i] - m); s += v[i]; }
#pragma unroll
    for (int o = 16; o > 0; o >>= 1) s += __shfl_xor_sync(0xffffffffu, s, o);
    if ((tid & 31) == 0) red[tid >> 5] = s;
    __syncthreads();
    if (tid == 0) {
        float t = 0.f;
#pragma unroll
        for (int i = 0; i < 8; i++) t += red[i];
        s_val = t;
    }
    __syncthreads();
    float inv = 1.0f / s_val;

    uint4 o;
    o.x = pack2h(v[0] * inv, v[1] * inv);
    o.y = pack2h(v[2] * inv, v[3] * inv);
    o.z = pack2h(v[4] * inv, v[5] * inv);
    o.w = pack2h(v[6] * inv, v[7] * inv);
    ((uint4*)(oh + row * SEQ))[tid] = o;
}

// ---------------------------------------------------------------------------
// fp16 single-pass warp-MMA GEMM. 128x128 tile, 128 threads (4 warps of
// 64x64), 2 CTAs/SM, BK=64 stages built from TWO 32-K sub-tiles in the
// byte-identical proven 80-B-stride layout (NOT the R9 stride-144 layout).
// Halves cp_wait / barrier / commit frequency vs BK=32. A- and B-fragment
// software pipelining as in Round 15.
// C = alpha * A @ op(B) (+bias) (relu); OMODE 0 = fp32 out (+residual),
// OMODE 2 = fp16 out.
// ---------------------------------------------------------------------------
#define A_STRIDE_B   80          // bytes per K-major fp16 row (32 data + 8 pad)
#define A_TILE_B     10240       // 128 * 80
#define BNN_STRIDE_B 272         // bytes per NN fp16 row (128 data + 8 pad)
#define BNN_TILE_B   8704        // 32 * 272
#define SUB_B        20480       // one 32-K sub-tile (A + B)
#define STAGE_B      40960       // 64-K stage = two sub-tiles
#define TC_SMEM      (2 * STAGE_B)   // 81920; 2 CTAs -> 163840 <= 228K
#define GEMM_THREADS 128

template<bool TRANSB>
__device__ __forceinline__ void load_sub(
    uint32_t sub, const __half* A, const __half* B,
    int rowBase, int colBase, int kb, int N, int K, int tid)
{
    const uint32_t aS = sub;
    const uint32_t bS = sub + A_TILE_B;

    // A: 128 rows x 32 cols fp16 = 512 16B chunks, 4 per thread
#pragma unroll
    for (int i = 0; i < 4; i++) {
        int id = tid + (i << 7);
        int r = id >> 2;
        int c8 = (id & 3) << 3;
        cp_async16(aS + (uint32_t)r * A_STRIDE_B + (uint32_t)(c8 << 1),
                   A + (size_t)(rowBase + r) * K + kb + c8);
    }
    if (TRANSB) {
#pragma unroll
        for (int i = 0; i < 4; i++) {
            int id = tid + (i << 7);
            int r = id >> 2;
            int c8 = (id & 3) << 3;
            cp_async16(bS + (uint32_t)r * A_STRIDE_B + (uint32_t)(c8 << 1),
                       B + (size_t)(colBase + r) * K + kb + c8);
        }
    } else {
        // B-NN: 32 k-rows x 128 n = 512 chunks
#pragma unroll
        for (int i = 0; i < 4; i++) {
            int id = tid + (i << 7);
            int r = id >> 4;
            int c8 = (id & 15) << 3;
            cp_async16(bS + (uint32_t)r * BNN_STRIDE_B + (uint32_t)(c8 << 1),
                       B + (size_t)(kb + r) * N + colBase + c8);
        }
    }
}

template<bool TRANSB>
__device__ __forceinline__ void load_chunk64(
    uint32_t stg, const __half* A, const __half* B,
    int rowBase, int colBase, int kb, int N, int K, int tid)
{
    load_sub<TRANSB>(stg,         A, B, rowBase, colBase, kb,      N, K, tid);
    load_sub<TRANSB>(stg + SUB_B, A, B, rowBase, colBase, kb + 32, N, K, tid);
    cp_commit();
}

// B-fragment smem offset for (ks, p) within one 32-K sub-tile
template<bool TRANSB>
__device__ __forceinline__ uint32_t b_off(int ks, int p, int lane, int wn)
{
    if (TRANSB)
        return (uint32_t)(wn * 64 + p * 16 + (lane & 7) + ((lane >> 4) & 1) * 8) * A_STRIDE_B
             + (uint32_t)(ks * 16 + ((lane >> 3) & 1) * 8) * 2;
    else
        return (uint32_t)(ks * 16 + (lane & 7) + ((lane >> 3) & 1) * 8) * BNN_STRIDE_B
             + (uint32_t)(wn * 64 + p * 16 + (lane >> 4) * 8) * 2;
}

template<bool TRANSB>
__device__ __forceinline__ void ldsm_b(uint32_t* r, uint32_t addr)
{
    if (TRANSB) ldsm_x4(r, addr); else ldsm_x4_t(r, addr);
}

template<bool TRANSB, bool RELU, int OMODE>
__global__ __launch_bounds__(GEMM_THREADS, 2)
void tc_gemm(const __half* __restrict__ A, const __half* __restrict__ B,
             float* __restrict__ Cf, __half* __restrict__ C16,
             const float* __restrict__ bias,
             const float* __restrict__ residual,
             int M, int N, int K, float alpha,
             long long strA, long long strB, long long strC, long long strBias)
{
    extern __shared__ char smem[];
    const uint32_t sb = smem_u32(smem);
    const int tid  = threadIdx.x;
    const int wid  = tid >> 5;
    const int lane = tid & 31;
    const int wm   = wid >> 1;      // 0..1 : rows [wm*64, +64)
    const int wn   = wid & 1;       // 0..1 : cols [wn*64, +64)

    long long bz = blockIdx.z;
    A += bz * strA;
    B += bz * strB;
    if (OMODE == 0) Cf += bz * strC; else C16 += bz * strC;
    if (bias) bias += bz * strBias;
    const float* Rres = (OMODE == 0 && residual) ? residual + bz * strC : nullptr;

    const int rowBase = blockIdx.y * 128;
    const int colBase = blockIdx.x * 128;

    float acc[4][8][4];
#pragma unroll
    for (int i = 0; i < 4; i++)
#pragma unroll
        for (int j = 0; j < 8; j++)
#pragma unroll
            for (int t = 0; t < 4; t++) acc[i][j][t] = 0.f;

    const int nch = K >> 6;    // 64-K stages (all K are multiples of 64)

    load_chunk64<TRANSB>(sb, A, B, rowBase, colBase, 0, N, K, tid);

    for (int c = 0; c < nch; c++) {
        const uint32_t stg = sb + (uint32_t)(c & 1) * STAGE_B;

        cp_wait_all();
        __syncthreads();

        if (c + 1 < nch)
            load_chunk64<TRANSB>(sb + (uint32_t)((c + 1) & 1) * STAGE_B,
                                 A, B, rowBase, colBase, (c + 1) * 64, N, K, tid);

#pragma unroll
        for (int s = 0; s < 2; s++) {
            const uint32_t aS = stg + (uint32_t)s * SUB_B;
            const uint32_t bS = aS + A_TILE_B;

            // A fragments: double-buffered across the two k-steps
            uint32_t af[2][4][4];
#pragma unroll
            for (int mt = 0; mt < 4; mt++) {
                uint32_t off = (uint32_t)(wm * 64 + mt * 16 + (lane & 15)) * A_STRIDE_B
                             + (uint32_t)((lane >> 4) * 8) * 2;   // ks = 0
                ldsm_x4(af[0][mt], aS + off);
            }

#pragma unroll
            for (int ks = 0; ks < 2; ks++) {
                if (ks == 0) {
                    // prefetch ks=1 A fragments under ks=0's MMAs
#pragma unroll
                    for (int mt = 0; mt < 4; mt++) {
                        uint32_t off = (uint32_t)(wm * 64 + mt * 16 + (lane & 15)) * A_STRIDE_B
                                     + (uint32_t)(16 + (lane >> 4) * 8) * 2;
                        ldsm_x4(af[1][mt], aS + off);
                    }
                }
                // software-pipelined B fragments
                uint32_t bf[2][4];
                ldsm_b<TRANSB>(bf[0], bS + b_off<TRANSB>(ks, 0, lane, wn));
#pragma unroll
                for (int p = 0; p < 4; p++) {
                    if (p < 3)
                        ldsm_b<TRANSB>(bf[(p + 1) & 1],
                                       bS + b_off<TRANSB>(ks, p + 1, lane, wn));
                    const uint32_t* bcur = bf[p & 1];
#pragma unroll
                    for (int mt = 0; mt < 4; mt++)
#pragma unroll
                        for (int g = 0; g < 2; g++)
                            mma_f16(acc[mt][p * 2 + g], af[ks][mt], bcur + 2 * g);
                }
            }
        }
        __syncthreads();
    }

    // ---- epilogue: warp covers rows [wm*64,+64) x cols [wn*64,+64)
#pragma unroll
    for (int mt = 0; mt < 4; mt++) {
        int r0 = rowBase + wm * 64 + mt * 16 + (lane >> 2);
#pragma unroll
        for (int ng = 0; ng < 8; ng++) {
            int col = colBase + wn * 64 + ng * 8 + (lane & 3) * 2;
            float2 v0, v1;
            v0.x = alpha * acc[mt][ng][0];
            v0.y = alpha * acc[mt][ng][1];
            v1.x = alpha * acc[mt][ng][2];
            v1.y = alpha * acc[mt][ng][3];
            if (bias) {
                float2 bb = *(const float2*)&bias[col];
                v0.x += bb.x; v0.y += bb.y;
                v1.x += bb.x; v1.y += bb.y;
            }
            if (RELU) {
                v0.x = fmaxf(v0.x, 0.f); v0.y = fmaxf(v0.y, 0.f);
                v1.x = fmaxf(v1.x, 0.f); v1.y = fmaxf(v1.y, 0.f);
            }
            if (OMODE == 0) {
                if (Rres) {
                    float2 q0 = *(const float2*)&Rres[(size_t)r0 * N + col];
                    float2 q1 = *(const float2*)&Rres[(size_t)(r0 + 8) * N + col];
                    v0.x += q0.x; v0.y += q0.y;
                    v1.x += q1.x; v1.y += q1.y;
                }
                *(float2*)&Cf[(size_t)r0 * N + col]       = v0;
                *(float2*)&Cf[(size_t)(r0 + 8) * N + col] = v1;
            } else {
                *(uint32_t*)&C16[(size_t)r0 * N + col]       = pack2h(v0.x, v0.y);
                *(uint32_t*)&C16[(size_t)(r0 + 8) * N + col] = pack2h(v1.x, v1.y);
            }
        }
    }
}

// ---------------------------------------------------------------------------
// Host launcher
// ---------------------------------------------------------------------------
extern "C" void kernel_launch(void* const* d_in, const int* in_sizes, int n_in,
                              void* d_out, int out_size)
{
    const int*   tokens = (const int*)  d_in[0];
    const float* emb    = (const float*)d_in[1];
    const float* Wq     = (const float*)d_in[2];
    const float* bq     = (const float*)d_in[3];
    const float* Wk     = (const float*)d_in[4];
    const float* bk     = (const float*)d_in[5];
    const float* Wv     = (const float*)d_in[6];
    const float* bv     = (const float*)d_in[7];
    const float* g1     = (const float*)d_in[8];
    const float* beta1  = (const float*)d_in[9];
    const float* g2     = (const float*)d_in[10];
    const float* beta2  = (const float*)d_in[11];
    const float* W1     = (const float*)d_in[12];
    const float* bm1    = (const float*)d_in[13];
    const float* W2     = (const float*)d_in[14];
    const float* bm2    = (const float*)d_in[15];

    float* x = (float*)d_out;

    __half *ln16, *qkv16, *sc16, *at16, *hid16, *Wqkv16, *W116, *W216;
    float *bqkv;
    cudaGetSymbolAddress((void**)&ln16,   g_ln16);
    cudaGetSymbolAddress((void**)&qkv16,  g_qkv16);
    cudaGetSymbolAddress((void**)&sc16,   g_sc16);
    cudaGetSymbolAddress((void**)&at16,   g_at16);
    cudaGetSymbolAddress((void**)&hid16,  g_hid16);
    cudaGetSymbolAddress((void**)&Wqkv16, g_Wqkv16);
    cudaGetSymbolAddress((void**)&W116,   g_W116);
    cudaGetSymbolAddress((void**)&W216,   g_W216);
    cudaGetSymbolAddress((void**)&bqkv,   g_bqkv);

    cudaFuncSetAttribute(tc_gemm<false, false, 2>,
                         cudaFuncAttributeMaxDynamicSharedMemorySize, TC_SMEM);
    cudaFuncSetAttribute(tc_gemm<true, false, 2>,
                         cudaFuncAttributeMaxDynamicSharedMemorySize, TC_SMEM);
    cudaFuncSetAttribute(tc_gemm<false, false, 0>,
                         cudaFuncAttributeMaxDynamicSharedMemorySize, TC_SMEM);
    cudaFuncSetAttribute(tc_gemm<false, true, 2>,
                         cudaFuncAttributeMaxDynamicSharedMemorySize, TC_SMEM);

    const long long TD = (long long)SEQ * D_MODEL;
    const long long SS = (long long)SEQ * SEQ;
    const float inv_sqrt_d = 0.03125f;

    __half* q16 = qkv16;
    __half* k16 = qkv16 + (size_t)NTOK * D_MODEL;
    __half* v16 = qkv16 + 2 * (size_t)NTOK * D_MODEL;

    // ---- prep: merged convs, concat, embed
    {
        int S4 = D_MODEL * D_MODEL / 4;
        int nq = NLAYERS * S4;
        int n1 = NLAYERS * D_MODEL * DFF / 4;
        dim3 gq(nq / 256, 1, 3);
        conv_qkv_kernel<<<gq, 256>>>(Wq, Wk, Wv, Wqkv16, nq, S4);
        dim3 g2d(n1 / 256, 1, 2);
        conv2_kernel<<<g2d, 256>>>(W1, W2, W116, W216, n1);
        concat_bias_kernel<<<NLAYERS * D_MODEL / 256, 256>>>(bq, bk, bv, bqkv);
    }
    embed_kernel<<<NTOK, 256>>>(tokens, emb, x);

    for (int l = 0; l < NLAYERS; l++) {
        size_t oQ = (size_t)l * 3 * D_MODEL * D_MODEL;
        size_t o1 = (size_t)l * D_MODEL * DFF;

        ln_kernel<<<NTOK, 256>>>(x, g1 + l * D_MODEL, beta1 + l * D_MODEL, ln16);

        // fused QKV -> fp16 q,k,v
        dim3 gQKV(D_MODEL / 128, NTOK / 128, 3);
        tc_gemm<false, false, 2><<<gQKV, GEMM_THREADS, TC_SMEM>>>(
            ln16, Wqkv16 + oQ, nullptr, qkv16,
            bqkv + (size_t)l * 3 * D_MODEL, nullptr,
            NTOK, D_MODEL, D_MODEL, 1.f,
            0, (long long)D_MODEL * D_MODEL, (long long)NTOK * D_MODEL, D_MODEL);

        // scores = q @ k^T / sqrt(D) -> fp16 logits
        dim3 gSC(SEQ / 128, SEQ / 128, BATCH);
        tc_gemm<true, false, 2><<<gSC, GEMM_THREADS, TC_SMEM>>>(
            q16, k16, nullptr, sc16, nullptr, nullptr,
            SEQ, SEQ, D_MODEL, inv_sqrt_d, TD, TD, SS, 0);

        softmax_kernel<<<BATCH * SEQ, 256>>>(sc16, at16);

        // x += attn @ v
        dim3 gAV(D_MODEL / 128, SEQ / 128, BATCH);
        tc_gemm<false, false, 0><<<gAV, GEMM_THREADS, TC_SMEM>>>(
            at16, v16, x, nullptr, nullptr, x,
            SEQ, D_MODEL, SEQ, 1.f, SS, TD, TD, 0);

        ln_kernel<<<NTOK, 256>>>(x, g2 + l * D_MODEL, beta2 + l * D_MODEL, ln16);

        // hid = relu(h2 @ W1 + bm1) -> fp16
        dim3 gM1(DFF / 128, NTOK / 128, 1);
        tc_gemm<false, true, 2><<<gM1, GEMM_THREADS, TC_SMEM>>>(
            ln16, W116 + o1, nullptr, hid16,
            bm1 + l * DFF, nullptr, NTOK, DFF, D_MODEL, 1.f, 0, 0, 0, 0);

        // x += hid @ W2 + bm2
        dim3 gM2(D_MODEL / 128, NTOK / 128, 1);
        tc_gemm<false, false, 0><<<gM2, GEMM_THREADS, TC_SMEM>>>(
            hid16, W216 + o1, x, nullptr,
            bm2 + l * D_MODEL, x, NTOK, D_MODEL, DFF, 1.f, 0, 0, 0, 0);
    }
}

// round 17
// speedup vs baseline: 1.1751x; 1.1751x over previous
#include <cuda_runtime.h>
#include <cuda_fp16.h>
#include <math.h>
#include <stdint.h>

// ---------------------------------------------------------------------------
// Problem constants
// ---------------------------------------------------------------------------
#define D_MODEL 1024
#define DFF     4096
#define NLAYERS 8
#define BATCH   4
#define SEQ     2048
#define NTOK    (BATCH * SEQ)      // 8192
#define EPS     1e-5f

// ---------------------------------------------------------------------------
// Device scratch (allocation-free rule: __device__ globals)
// ---------------------------------------------------------------------------
__device__ __half g_ln16 [NTOK * D_MODEL];
__device__ __half g_qkv16[3 * NTOK * D_MODEL];
__device__ __half g_sc16 [BATCH * SEQ * SEQ];     // fp16 attention logits
__device__ __half g_at16 [BATCH * SEQ * SEQ];     // fp16 attention weights
__device__ __half g_hid16[NTOK * DFF];
// fp16 weights; QKV interleaved per layer: [L][3][D*D]
__device__ __half g_Wqkv16[NLAYERS * 3 * D_MODEL * D_MODEL];
__device__ __half g_W116[NLAYERS * D_MODEL * DFF];
__device__ __half g_W216[NLAYERS * DFF * D_MODEL];
__device__ float  g_bqkv[NLAYERS * 3 * D_MODEL];

// ---------------------------------------------------------------------------
// PTX helpers
// ---------------------------------------------------------------------------
__device__ __forceinline__ uint32_t smem_u32(const void* p) {
    uint32_t a;
    asm("{ .reg .u64 t; cvta.to.shared.u64 t, %1; cvt.u32.u64 %0, t; }"
        : "=r"(a) : "l"(p));
    return a;
}

__device__ __forceinline__ void ldsm_x4(uint32_t* r, uint32_t addr) {
    asm volatile("ldmatrix.sync.aligned.m8n8.x4.shared.b16 {%0,%1,%2,%3}, [%4];"
                 : "=r"(r[0]), "=r"(r[1]), "=r"(r[2]), "=r"(r[3]) : "r"(addr));
}

__device__ __forceinline__ void ldsm_x4_t(uint32_t* r, uint32_t addr) {
    asm volatile("ldmatrix.sync.aligned.m8n8.x4.trans.shared.b16 {%0,%1,%2,%3}, [%4];"
                 : "=r"(r[0]), "=r"(r[1]), "=r"(r[2]), "=r"(r[3]) : "r"(addr));
}

__device__ __forceinline__ void mma_f16(float* c, const uint32_t* a, const uint32_t* b) {
    asm volatile(
        "mma.sync.aligned.m16n8k16.row.col.f32.f16.f16.f32 "
        "{%0,%1,%2,%3}, {%4,%5,%6,%7}, {%8,%9}, {%0,%1,%2,%3};"
        : "+f"(c[0]), "+f"(c[1]), "+f"(c[2]), "+f"(c[3])
        : "r"(a[0]), "r"(a[1]), "r"(a[2]), "r"(a[3]), "r"(b[0]), "r"(b[1]));
}

__device__ __forceinline__ void cp_async16(uint32_t saddr, const void* gptr) {
    asm volatile("cp.async.cg.shared.global [%0], [%1], 16;"
                 :: "r"(saddr), "l"(gptr) : "memory");
}
__device__ __forceinline__ void cp_commit() {
    asm volatile("cp.async.commit_group;" ::: "memory");
}
__device__ __forceinline__ void cp_wait_all() {
    asm volatile("cp.async.wait_group 0;" ::: "memory");
}

__device__ __forceinline__ uint32_t pack2h(float a, float b) {
    __half ha = __float2half_rn(a), hb = __float2half_rn(b);
    return ((uint32_t)__half_as_ushort(hb) << 16) | __half_as_ushort(ha);
}

// ---------------------------------------------------------------------------
// Weight conversion kernels (fp32 -> fp16), merged
// ---------------------------------------------------------------------------
__global__ __launch_bounds__(256)
void conv_qkv_kernel(const float* __restrict__ Wq,
                     const float* __restrict__ Wk,
                     const float* __restrict__ Wv,
                     __half* __restrict__ out, int n4, int S4)
{
    int i = blockIdx.x * 256 + threadIdx.x;
    if (i >= n4) return;
    int j = blockIdx.z;
    const float* in = (j == 0) ? Wq : (j == 1) ? Wk : Wv;
    int l = i / S4;
    int rem = i - l * S4;
    int d = (l * 3 + j) * S4 + rem;
    float4 v = ((const float4*)in)[i];
    ((uint2*)out)[d] = make_uint2(pack2h(v.x, v.y), pack2h(v.z, v.w));
}

__global__ __launch_bounds__(256)
void conv2_kernel(const float* __restrict__ W1, const float* __restrict__ W2,
                  __half* __restrict__ o1, __half* __restrict__ o2, int n4)
{
    int i = blockIdx.x * 256 + threadIdx.x;
    if (i >= n4) return;
    const float* in = blockIdx.z ? W2 : W1;
    __half* out = blockIdx.z ? o2 : o1;
    float4 v = ((const float4*)in)[i];
    ((uint2*)out)[i] = make_uint2(pack2h(v.x, v.y), pack2h(v.z, v.w));
}

__global__ __launch_bounds__(256)
void concat_bias_kernel(const float* __restrict__ bq,
                        const float* __restrict__ bk,
                        const float* __restrict__ bv,
                        float* __restrict__ out)
{
    int i = blockIdx.x * 256 + threadIdx.x;
    int l = i / D_MODEL;
    int d = i - l * D_MODEL;
    out[(l * 3 + 0) * D_MODEL + d] = bq[i];
    out[(l * 3 + 1) * D_MODEL + d] = bk[i];
    out[(l * 3 + 2) * D_MODEL + d] = bv[i];
}

// ---------------------------------------------------------------------------
// Embedding + sinusoidal PE
// ---------------------------------------------------------------------------
__global__ __launch_bounds__(256)
void embed_kernel(const int* __restrict__ tokens,
                  const float* __restrict__ emb,
                  float* __restrict__ out)
{
    int row = blockIdx.x;
    int s   = row & (SEQ - 1);
    int tok = tokens[row];
    int d   = threadIdx.x * 4;

    float4 e = *(const float4*)&emb[(size_t)tok * D_MODEL + d];
    float o[4] = { e.x, e.y, e.z, e.w };
#pragma unroll
    for (int i = 0; i < 4; i++) {
        int dd = d + i;
        float freq = expf((float)(dd & ~1) * (-9.210340371976184f / (float)D_MODEL));
        float a = (float)s * freq;
        o[i] += (dd & 1) ? cosf(a) : sinf(a);
    }
    *(float4*)&out[(size_t)row * D_MODEL + d] = make_float4(o[0], o[1], o[2], o[3]);
}

// ---------------------------------------------------------------------------
// LayerNorm: fp32 in -> fp16 out
// ---------------------------------------------------------------------------
__global__ __launch_bounds__(256)
void ln_kernel(const float* __restrict__ x,
               const float* __restrict__ g,
               const float* __restrict__ b,
               __half* __restrict__ out)
{
    __shared__ float red[8];
    __shared__ float s_stat;

    int row = blockIdx.x;
    int tid = threadIdx.x;
    const float4* xr = (const float4*)(x + (size_t)row * D_MODEL);
    float4 v = xr[tid];

    float s = v.x + v.y + v.z + v.w;
#pragma unroll
    for (int o = 16; o > 0; o >>= 1) s += __shfl_xor_sync(0xffffffffu, s, o);
    if ((tid & 31) == 0) red[tid >> 5] = s;
    __syncthreads();
    if (tid == 0) {
        float t = 0.f;
#pragma unroll
        for (int i = 0; i < 8; i++) t += red[i];
        s_stat = t * (1.0f / D_MODEL);
    }
    __syncthreads();
    float mean = s_stat;

    float4 d;
    d.x = v.x - mean; d.y = v.y - mean; d.z = v.z - mean; d.w = v.w - mean;

    float s2 = d.x * d.x + d.y * d.y + d.z * d.z + d.w * d.w;
#pragma unroll
    for (int o = 16; o > 0; o >>= 1) s2 += __shfl_xor_sync(0xffffffffu, s2, o);
    if ((tid & 31) == 0) red[tid >> 5] = s2;
    __syncthreads();
    if (tid == 0) {
        float t = 0.f;
#pragma unroll
        for (int i = 0; i < 8; i++) t += red[i];
        s_stat = rsqrtf(t * (1.0f / D_MODEL) + EPS);
    }
    __syncthreads();
    float rstd = s_stat;

    float4 gg = *(const float4*)&g[tid * 4];
    float4 bb = *(const float4*)&b[tid * 4];
    float4 o4;
    o4.x = d.x * rstd * gg.x + bb.x;
    o4.y = d.y * rstd * gg.y + bb.y;
    o4.z = d.z * rstd * gg.z + bb.z;
    o4.w = d.w * rstd * gg.w + bb.w;

    ((uint2*)(out + (size_t)row * D_MODEL))[tid] =
        make_uint2(pack2h(o4.x, o4.y), pack2h(o4.z, o4.w));
}

// ---------------------------------------------------------------------------
// Softmax: fp16 logits in -> fp16 weights out
// ---------------------------------------------------------------------------
__device__ __forceinline__ void unpack8(uint4 u, float* f) {
    float2 a = __half22float2(*(__half2*)&u.x);
    float2 b = __half22float2(*(__half2*)&u.y);
    float2 c = __half22float2(*(__half2*)&u.z);
    float2 d = __half22float2(*(__half2*)&u.w);
    f[0] = a.x; f[1] = a.y; f[2] = b.x; f[3] = b.y;
    f[4] = c.x; f[5] = c.y; f[6] = d.x; f[7] = d.y;
}

__global__ __launch_bounds__(256)
void softmax_kernel(const __half* __restrict__ sc, __half* __restrict__ oh)
{
    __shared__ float red[8];
    __shared__ float s_val;

    size_t row = blockIdx.x;
    const uint4* p = (const uint4*)(sc + row * SEQ);
    int tid = threadIdx.x;

    float v[8];
    unpack8(p[tid], v);

    float m = v[0];
#pragma unroll
    for (int i = 1; i < 8; i++) m = fmaxf(m, v[i]);
#pragma unroll
    for (int o = 16; o > 0; o >>= 1) m = fmaxf(m, __shfl_xor_sync(0xffffffffu, m, o));
    if ((tid & 31) == 0) red[tid >> 5] = m;
    __syncthreads();
    if (tid == 0) {
        float t = red[0];
#pragma unroll
        for (int i = 1; i < 8; i++) t = fmaxf(t, red[i]);
        s_val = t;
    }
    __syncthreads();
    m = s_val;

    float s = 0.f;
#pragma unroll
    for (int i = 0; i < 8; i++) { v[i] = __expf(v[i] - m); s += v[i]; }
#pragma unroll
    for (int o = 16; o > 0; o >>= 1) s += __shfl_xor_sync(0xffffffffu, s, o);
    if ((tid & 31) == 0) red[tid >> 5] = s;
    __syncthreads();
    if (tid == 0) {
        float t = 0.f;
#pragma unroll
        for (int i = 0; i < 8; i++) t += red[i];
        s_val = t;
    }
    __syncthreads();
    float inv = 1.0f / s_val;

    uint4 o;
    o.x = pack2h(v[0] * inv, v[1] * inv);
    o.y = pack2h(v[2] * inv, v[3] * inv);
    o.z = pack2h(v[4] * inv, v[5] * inv);
    o.w = pack2h(v[6] * inv, v[7] * inv);
    ((uint4*)(oh + row * SEQ))[tid] = o;
}

// ---------------------------------------------------------------------------
// fp16 single-pass warp-MMA GEMM. 128x128 tile, 128 threads (4 warps of
// 64x64), 2 CTAs/SM, BK=32, double-buffered cp.async, A-fragment
// double-buffering across k-steps + B-fragment software pipelining.
// (Round-15 configuration -- empirically optimal; BK coarsening regresses.)
// C = alpha * A @ op(B) (+bias) (relu); OMODE 0 = fp32 out (+residual),
// OMODE 2 = fp16 out.
// ---------------------------------------------------------------------------
#define A_STRIDE_B   80          // bytes per K-major fp16 row (32 data + 8 pad)
#define A_TILE_B     10240       // 128 * 80
#define BNN_STRIDE_B 272         // bytes per NN fp16 row (128 data + 8 pad)
#define BNN_TILE_B   8704        // 32 * 272
#define STAGE_B      20480
#define TC_SMEM      (2 * STAGE_B)   // 40960
#define GEMM_THREADS 128

template<bool TRANSB>
__device__ __forceinline__ void load_chunk(
    uint32_t stg, const __half* A, const __half* B,
    int rowBase, int colBase, int kb, int N, int K, int tid)
{
    const uint32_t aS = stg;
    const uint32_t bS = stg + A_TILE_B;

    // A: 128 rows x 32 cols fp16 = 512 16B chunks, 4 per thread
#pragma unroll
    for (int i = 0; i < 4; i++) {
        int id = tid + (i << 7);
        int r = id >> 2;
        int c8 = (id & 3) << 3;
        cp_async16(aS + (uint32_t)r * A_STRIDE_B + (uint32_t)(c8 << 1),
                   A + (size_t)(rowBase + r) * K + kb + c8);
    }
    if (TRANSB) {
#pragma unroll
        for (int i = 0; i < 4; i++) {
            int id = tid + (i << 7);
            int r = id >> 2;
            int c8 = (id & 3) << 3;
            cp_async16(bS + (uint32_t)r * A_STRIDE_B + (uint32_t)(c8 << 1),
                       B + (size_t)(colBase + r) * K + kb + c8);
        }
    } else {
        // B-NN: 32 k-rows x 128 n = 512 chunks
#pragma unroll
        for (int i = 0; i < 4; i++) {
            int id = tid + (i << 7);
            int r = id >> 4;
            int c8 = (id & 15) << 3;
            cp_async16(bS + (uint32_t)r * BNN_STRIDE_B + (uint32_t)(c8 << 1),
                       B + (size_t)(kb + r) * N + colBase + c8);
        }
    }
    cp_commit();
}

// B-fragment smem offset for (ks, p)
template<bool TRANSB>
__device__ __forceinline__ uint32_t b_off(int ks, int p, int lane, int wn)
{
    if (TRANSB)
        return (uint32_t)(wn * 64 + p * 16 + (lane & 7) + ((lane >> 4) & 1) * 8) * A_STRIDE_B
             + (uint32_t)(ks * 16 + ((lane >> 3) & 1) * 8) * 2;
    else
        return (uint32_t)(ks * 16 + (lane & 7) + ((lane >> 3) & 1) * 8) * BNN_STRIDE_B
             + (uint32_t)(wn * 64 + p * 16 + (lane >> 4) * 8) * 2;
}

template<bool TRANSB>
__device__ __forceinline__ void ldsm_b(uint32_t* r, uint32_t addr)
{
    if (TRANSB) ldsm_x4(r, addr); else ldsm_x4_t(r, addr);
}

template<bool TRANSB, bool RELU, int OMODE>
__global__ __launch_bounds__(GEMM_THREADS, 2)
void tc_gemm(const __half* __restrict__ A, const __half* __restrict__ B,
             float* __restrict__ Cf, __half* __restrict__ C16,
             const float* __restrict__ bias,
             const float* __restrict__ residual,
             int M, int N, int K, float alpha,
             long long strA, long long strB, long long strC, long long strBias)
{
    extern __shared__ char smem[];
    const uint32_t sb = smem_u32(smem);
    const int tid  = threadIdx.x;
    const int wid  = tid >> 5;
    const int lane = tid & 31;
    const int wm   = wid >> 1;      // 0..1 : rows [wm*64, +64)
    const int wn   = wid & 1;       // 0..1 : cols [wn*64, +64)

    long long bz = blockIdx.z;
    A += bz * strA;
    B += bz * strB;
    if (OMODE == 0) Cf += bz * strC; else C16 += bz * strC;
    if (bias) bias += bz * strBias;
    const float* Rres = (OMODE == 0 && residual) ? residual + bz * strC : nullptr;

    const int rowBase = blockIdx.y * 128;
    const int colBase = blockIdx.x * 128;

    float acc[4][8][4];
#pragma unroll
    for (int i = 0; i < 4; i++)
#pragma unroll
        for (int j = 0; j < 8; j++)
#pragma unroll
            for (int t = 0; t < 4; t++) acc[i][j][t] = 0.f;

    const int nch = K >> 5;

    load_chunk<TRANSB>(sb, A, B, rowBase, colBase, 0, N, K, tid);

    for (int c = 0; c < nch; c++) {
        const uint32_t stg = sb + (uint32_t)(c & 1) * STAGE_B;
        const uint32_t aS = stg;
        const uint32_t bS = stg + A_TILE_B;

        cp_wait_all();
        __syncthreads();

        if (c + 1 < nch)
            load_chunk<TRANSB>(sb + (uint32_t)((c + 1) & 1) * STAGE_B,
                               A, B, rowBase, colBase, (c + 1) * 32, N, K, tid);

        // A fragments: double-buffered across the two k-steps
        uint32_t af[2][4][4];
#pragma unroll
        for (int mt = 0; mt < 4; mt++) {
            uint32_t off = (uint32_t)(wm * 64 + mt * 16 + (lane & 15)) * A_STRIDE_B
                         + (uint32_t)((lane >> 4) * 8) * 2;   // ks = 0
            ldsm_x4(af[0][mt], aS + off);
        }

#pragma unroll
        for (int ks = 0; ks < 2; ks++) {
            if (ks == 0) {
                // prefetch ks=1 A fragments under ks=0's MMAs
#pragma unroll
                for (int mt = 0; mt < 4; mt++) {
                    uint32_t off = (uint32_t)(wm * 64 + mt * 16 + (lane & 15)) * A_STRIDE_B
                                 + (uint32_t)(16 + (lane >> 4) * 8) * 2;
                    ldsm_x4(af[1][mt], aS + off);
                }
            }
            // software-pipelined B fragments
            uint32_t bf[2][4];
            ldsm_b<TRANSB>(bf[0], bS + b_off<TRANSB>(ks, 0, lane, wn));
#pragma unroll
            for (int p = 0; p < 4; p++) {
                if (p < 3)
                    ldsm_b<TRANSB>(bf[(p + 1) & 1],
                                   bS + b_off<TRANSB>(ks, p + 1, lane, wn));
                const uint32_t* bcur = bf[p & 1];
#pragma unroll
                for (int mt = 0; mt < 4; mt++)
#pragma unroll
                    for (int g = 0; g < 2; g++)
                        mma_f16(acc[mt][p * 2 + g], af[ks][mt], bcur + 2 * g);
            }
        }
        __syncthreads();
    }

    // ---- epilogue: warp covers rows [wm*64,+64) x cols [wn*64,+64)
#pragma unroll
    for (int mt = 0; mt < 4; mt++) {
        int r0 = rowBase + wm * 64 + mt * 16 + (lane >> 2);
#pragma unroll
        for (int ng = 0; ng < 8; ng++) {
            int col = colBase + wn * 64 + ng * 8 + (lane & 3) * 2;
            float2 v0, v1;
            v0.x = alpha * acc[mt][ng][0];
            v0.y = alpha * acc[mt][ng][1];
            v1.x = alpha * acc[mt][ng][2];
            v1.y = alpha * acc[mt][ng][3];
            if (bias) {
                float2 bb = *(const float2*)&bias[col];
                v0.x += bb.x; v0.y += bb.y;
                v1.x += bb.x; v1.y += bb.y;
            }
            if (RELU) {
                v0.x = fmaxf(v0.x, 0.f); v0.y = fmaxf(v0.y, 0.f);
                v1.x = fmaxf(v1.x, 0.f); v1.y = fmaxf(v1.y, 0.f);
            }
            if (OMODE == 0) {
                if (Rres) {
                    float2 q0 = *(const float2*)&Rres[(size_t)r0 * N + col];
                    float2 q1 = *(const float2*)&Rres[(size_t)(r0 + 8) * N + col];
                    v0.x += q0.x; v0.y += q0.y;
                    v1.x += q1.x; v1.y += q1.y;
                }
                *(float2*)&Cf[(size_t)r0 * N + col]       = v0;
                *(float2*)&Cf[(size_t)(r0 + 8) * N + col] = v1;
            } else {
                *(uint32_t*)&C16[(size_t)r0 * N + col]       = pack2h(v0.x, v0.y);
                *(uint32_t*)&C16[(size_t)(r0 + 8) * N + col] = pack2h(v1.x, v1.y);
            }
        }
    }
}

// ---------------------------------------------------------------------------
// Host launcher
// ---------------------------------------------------------------------------
extern "C" void kernel_launch(void* const* d_in, const int* in_sizes, int n_in,
                              void* d_out, int out_size)
{
    const int*   tokens = (const int*)  d_in[0];
    const float* emb    = (const float*)d_in[1];
    const float* Wq     = (const float*)d_in[2];
    const float* bq     = (const float*)d_in[3];
    const float* Wk     = (const float*)d_in[4];
    const float* bk     = (const float*)d_in[5];
    const float* Wv     = (const float*)d_in[6];
    const float* bv     = (const float*)d_in[7];
    const float* g1     = (const float*)d_in[8];
    const float* beta1  = (const float*)d_in[9];
    const float* g2     = (const float*)d_in[10];
    const float* beta2  = (const float*)d_in[11];
    const float* W1     = (const float*)d_in[12];
    const float* bm1    = (const float*)d_in[13];
    const float* W2     = (const float*)d_in[14];
    const float* bm2    = (const float*)d_in[15];

    float* x = (float*)d_out;

    __half *ln16, *qkv16, *sc16, *at16, *hid16, *Wqkv16, *W116, *W216;
    float *bqkv;
    cudaGetSymbolAddress((void**)&ln16,   g_ln16);
    cudaGetSymbolAddress((void**)&qkv16,  g_qkv16);
    cudaGetSymbolAddress((void**)&sc16,   g_sc16);
    cudaGetSymbolAddress((void**)&at16,   g_at16);
    cudaGetSymbolAddress((void**)&hid16,  g_hid16);
    cudaGetSymbolAddress((void**)&Wqkv16, g_Wqkv16);
    cudaGetSymbolAddress((void**)&W116,   g_W116);
    cudaGetSymbolAddress((void**)&W216,   g_W216);
    cudaGetSymbolAddress((void**)&bqkv,   g_bqkv);

    cudaFuncSetAttribute(tc_gemm<false, false, 2>,
                         cudaFuncAttributeMaxDynamicSharedMemorySize, TC_SMEM);
    cudaFuncSetAttribute(tc_gemm<true, false, 2>,
                         cudaFuncAttributeMaxDynamicSharedMemorySize, TC_SMEM);
    cudaFuncSetAttribute(tc_gemm<false, false, 0>,
                         cudaFuncAttributeMaxDynamicSharedMemorySize, TC_SMEM);
    cudaFuncSetAttribute(tc_gemm<false, true, 2>,
                         cudaFuncAttributeMaxDynamicSharedMemorySize, TC_SMEM);

    const long long TD = (long long)SEQ * D_MODEL;
    const long long SS = (long long)SEQ * SEQ;
    const float inv_sqrt_d = 0.03125f;

    __half* q16 = qkv16;
    __half* k16 = qkv16 + (size_t)NTOK * D_MODEL;
    __half* v16 = qkv16 + 2 * (size_t)NTOK * D_MODEL;

    // ---- prep: merged convs, concat, embed
    {
        int S4 = D_MODEL * D_MODEL / 4;
        int nq = NLAYERS * S4;
        int n1 = NLAYERS * D_MODEL * DFF / 4;
        dim3 gq(nq / 256, 1, 3);
        conv_qkv_kernel<<<gq, 256>>>(Wq, Wk, Wv, Wqkv16, nq, S4);
        dim3 g2d(n1 / 256, 1, 2);
        conv2_kernel<<<g2d, 256>>>(W1, W2, W116, W216, n1);
        concat_bias_kernel<<<NLAYERS * D_MODEL / 256, 256>>>(bq, bk, bv, bqkv);
    }
    embed_kernel<<<NTOK, 256>>>(tokens, emb, x);

    for (int l = 0; l < NLAYERS; l++) {
        size_t oQ = (size_t)l * 3 * D_MODEL * D_MODEL;
        size_t o1 = (size_t)l * D_MODEL * DFF;

        ln_kernel<<<NTOK, 256>>>(x, g1 + l * D_MODEL, beta1 + l * D_MODEL, ln16);

        // fused QKV -> fp16 q,k,v
        dim3 gQKV(D_MODEL / 128, NTOK / 128, 3);
        tc_gemm<false, false, 2><<<gQKV, GEMM_THREADS, TC_SMEM>>>(
            ln16, Wqkv16 + oQ, nullptr, qkv16,
            bqkv + (size_t)l * 3 * D_MODEL, nullptr,
            NTOK, D_MODEL, D_MODEL, 1.f,
            0, (long long)D_MODEL * D_MODEL, (long long)NTOK * D_MODEL, D_MODEL);

        // scores = q @ k^T / sqrt(D) -> fp16 logits
        dim3 gSC(SEQ / 128, SEQ / 128, BATCH);
        tc_gemm<true, false, 2><<<gSC, GEMM_THREADS, TC_SMEM>>>(
            q16, k16, nullptr, sc16, nullptr, nullptr,
            SEQ, SEQ, D_MODEL, inv_sqrt_d, TD, TD, SS, 0);

        softmax_kernel<<<BATCH * SEQ, 256>>>(sc16, at16);

        // x += attn @ v
        dim3 gAV(D_MODEL / 128, SEQ / 128, BATCH);
        tc_gemm<false, false, 0><<<gAV, GEMM_THREADS, TC_SMEM>>>(
            at16, v16, x, nullptr, nullptr, x,
            SEQ, D_MODEL, SEQ, 1.f, SS, TD, TD, 0);

        ln_kernel<<<NTOK, 256>>>(x, g2 + l * D_MODEL, beta2 + l * D_MODEL, ln16);

        // hid = relu(h2 @ W1 + bm1) -> fp16
        dim3 gM1(DFF / 128, NTOK / 128, 1);
        tc_gemm<false, true, 2><<<gM1, GEMM_THREADS, TC_SMEM>>>(
            ln16, W116 + o1, nullptr, hid16,
            bm1 + l * DFF, nullptr, NTOK, DFF, D_MODEL, 1.f, 0, 0, 0, 0);

        // x += hid @ W2 + bm2
        dim3 gM2(D_MODEL / 128, NTOK / 128, 1);
        tc_gemm<false, false, 0><<<gM2, GEMM_THREADS, TC_SMEM>>>(
            hid16, W216 + o1, x, nullptr,
            bm2 + l * D_MODEL, x, NTOK, D_MODEL, DFF, 1.f, 0, 0, 0, 0);
    }
}